// round 16
// baseline (speedup 1.0000x reference)
#include <cuda_runtime.h>

#define Hh 4
#define Oo 32
#define Mm 128
#define M2 256
#define Dd 16
#define Bb 1024
#define HO 128
#define HOB (HO*Bb)
#define JIT 1e-4f
#define LDA 129

// ---------------- f32x2 helpers ----------------
__device__ __forceinline__ unsigned long long pk2(float lo, float hi) {
    unsigned long long r;
    asm("mov.b64 %0, {%1, %2};" : "=l"(r) : "f"(lo), "f"(hi));
    return r;
}
__device__ __forceinline__ float2 upk2(unsigned long long v) {
    float2 r;
    asm("mov.b64 {%0, %1}, %2;" : "=f"(r.x), "=f"(r.y) : "l"(v));
    return r;
}
__device__ __forceinline__ unsigned long long ffma2(unsigned long long a, unsigned long long b, unsigned long long c) {
    unsigned long long d;
    asm("fma.rn.f32x2 %0, %1, %2, %3;" : "=l"(d) : "l"(a), "l"(b), "l"(c));
    return d;
}

// ---------------- device scratch ----------------
__device__ float g_sf2[Hh];
__device__ float g_invls[Hh][Dd];
__device__ float g_Xs[Hh][Bb][Dd];
__device__ float g_xn[Hh][Bb];
__device__ float g_Zs[HO][M2][Dd];
__device__ float g_zn[HO][M2];
__device__ float g_kuu2[HO][M2][M2];
__device__ float g_cov[HO][M2][M2];
__device__ float g_Wt[HO][M2][M2];     // Wt[k][i] = Linv256[i][k]
__device__ float g_R[HO][M2][M2];
__device__ float g_vm[HO][M2];
__device__ float g_mj[HO][M2];
__device__ float g_yv[HO][Mm];
__device__ float g_kx[HO][M2][Bb];
__device__ float g_a[HO][M2][Bb];
__device__ float g_X1[HO][Mm][Mm];
__device__ float g_X2[HO][Mm][Mm];
__device__ float g_W11[HO][Mm][Mm];
__device__ float g_T1[HO][Mm][Mm];
__device__ float g_AtX[HO][Mm][Mm];
__device__ float g_schur[HO][Mm][Mm];
__device__ float g_L11p[HO][Mm][Mm];
__device__ float g_L21p[HO][Mm][Mm];
__device__ float g_L22p[HO][Mm][Mm];
__device__ float g_d1p[2][HO][Bb];
__device__ float g_d2p[2][HO][Bb];
__device__ float g_mup[2][HO][Bb];

// ---------------- serial building blocks (dense 128, LD=129, blockDim-agnostic) ----------------
__device__ void chol128(float* Ls, float* dinv, int t) {
    for (int j = 0; j < Mm; j++) {
        if (t < 32) {
            float s = 0.0f;
            for (int k = t; k < j; k += 32) { float v = Ls[j * LDA + k]; s += v * v; }
            for (int w = 16; w; w >>= 1) s += __shfl_down_sync(0xffffffffu, s, w);
            if (t == 0) {
                float d = sqrtf(Ls[j * LDA + j] - s);
                Ls[j * LDA + j] = d;
                dinv[j] = 1.0f / d;
            }
        }
        __syncthreads();
        int i = j + 1 + t;
        if (i < Mm) {
            float s0 = 0, s1 = 0, s2 = 0, s3 = 0;
            int k = 0;
            for (; k + 3 < j; k += 4) {
                s0 += Ls[i * LDA + k]     * Ls[j * LDA + k];
                s1 += Ls[i * LDA + k + 1] * Ls[j * LDA + k + 1];
                s2 += Ls[i * LDA + k + 2] * Ls[j * LDA + k + 2];
                s3 += Ls[i * LDA + k + 3] * Ls[j * LDA + k + 3];
            }
            for (; k < j; k++) s0 += Ls[i * LDA + k] * Ls[j * LDA + k];
            Ls[i * LDA + j] = (Ls[i * LDA + j] - ((s0 + s1) + (s2 + s3))) * dinv[j];
        }
        __syncthreads();
    }
}

__device__ void trtri128_blocked(float* Ls, float* dinv, int t) {
    if (t == 0) Ls[0] = dinv[0];
    if (t == 1) Ls[64 * LDA + 64] = dinv[64];
    __syncthreads();
    for (int i = 1; i < 64; i++) {
        float v = 0.0f;
        bool actA = (t < i);
        int u = t - 128;
        bool actB = (u >= 0 && u < i);
        if (actA) {
            float s0 = 0, s1 = 0, s2 = 0, s3 = 0;
            int k = t;
            for (; k + 3 < i; k += 4) {
                s0 += Ls[i * LDA + k]     * Ls[(k)     * LDA + t];
                s1 += Ls[i * LDA + k + 1] * Ls[(k + 1) * LDA + t];
                s2 += Ls[i * LDA + k + 2] * Ls[(k + 2) * LDA + t];
                s3 += Ls[i * LDA + k + 3] * Ls[(k + 3) * LDA + t];
            }
            for (; k < i; k++) s0 += Ls[i * LDA + k] * Ls[k * LDA + t];
            v = -dinv[i] * ((s0 + s1) + (s2 + s3));
        } else if (actB) {
            const int O = 64 * LDA + 64;
            float s0 = 0, s1 = 0, s2 = 0, s3 = 0;
            int k = u;
            for (; k + 3 < i; k += 4) {
                s0 += Ls[O + i * LDA + k]     * Ls[O + (k)     * LDA + u];
                s1 += Ls[O + i * LDA + k + 1] * Ls[O + (k + 1) * LDA + u];
                s2 += Ls[O + i * LDA + k + 2] * Ls[O + (k + 2) * LDA + u];
                s3 += Ls[O + i * LDA + k + 3] * Ls[O + (k + 3) * LDA + u];
            }
            for (; k < i; k++) s0 += Ls[O + i * LDA + k] * Ls[O + k * LDA + u];
            v = -dinv[64 + i] * ((s0 + s1) + (s2 + s3));
        }
        __syncthreads();
        if (actA) Ls[i * LDA + t] = v;
        if (actB) Ls[(64 + i) * LDA + 64 + u] = v;
        if (t == 0) Ls[i * LDA + i] = dinv[i];
        if (t == 1) Ls[(64 + i) * LDA + 64 + i] = dinv[64 + i];
        __syncthreads();
    }
    for (int e = t; e < 64 * 64; e += blockDim.x) {
        int r = e >> 6, c = e & 63;
        if (c > r) { Ls[r * LDA + c] = 0.0f; Ls[(64 + r) * LDA + 64 + c] = 0.0f; }
        Ls[r * LDA + 64 + c] = 0.0f;
    }
    __syncthreads();
    int tx = t & 15, ty = (t >> 4) & 15;
    bool act = (t < 256);
    float T[4][4];
#pragma unroll
    for (int m = 0; m < 4; m++)
#pragma unroll
        for (int n = 0; n < 4; n++) T[m][n] = 0.0f;
    if (act) {
        for (int k = 0; k < 64; k++) {
            float a[4], b[4];
#pragma unroll
            for (int m = 0; m < 4; m++) a[m] = Ls[(64 + ty + 16 * m) * LDA + k];
#pragma unroll
            for (int n = 0; n < 4; n++) b[n] = Ls[k * LDA + tx + 16 * n];
#pragma unroll
            for (int m = 0; m < 4; m++)
#pragma unroll
                for (int n = 0; n < 4; n++) T[m][n] += a[m] * b[n];
        }
    }
    __syncthreads();
    if (act) {
#pragma unroll
        for (int m = 0; m < 4; m++)
#pragma unroll
            for (int n = 0; n < 4; n++) Ls[(64 + ty + 16 * m) * LDA + tx + 16 * n] = T[m][n];
    }
    __syncthreads();
#pragma unroll
    for (int m = 0; m < 4; m++)
#pragma unroll
        for (int n = 0; n < 4; n++) T[m][n] = 0.0f;
    if (act) {
        for (int k = 0; k < 64; k++) {
            float a[4], b[4];
#pragma unroll
            for (int m = 0; m < 4; m++) a[m] = Ls[(64 + ty + 16 * m) * LDA + 64 + k];
#pragma unroll
            for (int n = 0; n < 4; n++) b[n] = Ls[(64 + k) * LDA + tx + 16 * n];
#pragma unroll
            for (int m = 0; m < 4; m++)
#pragma unroll
                for (int n = 0; n < 4; n++) T[m][n] -= a[m] * b[n];
        }
    }
    __syncthreads();
    if (act) {
#pragma unroll
        for (int m = 0; m < 4; m++)
#pragma unroll
            for (int n = 0; n < 4; n++) Ls[(64 + ty + 16 * m) * LDA + tx + 16 * n] = T[m][n];
    }
    __syncthreads();
}

// ---------------- prep ----------------
__global__ void k_prep_theta(const float* __restrict__ theta) {
    int t = threadIdx.x;
    if (t < Hh * (Dd + 1)) {
        int h = t / (Dd + 1), c = t % (Dd + 1);
        float v = theta[t];
        if (c == 0) g_sf2[h] = expf(v);
        else        g_invls[h][c - 1] = expf(-v);
    }
}

// prep_z (blocks 0..127) U prep_x (blocks 128..143)
__global__ void k_prep(const float* __restrict__ z, const float* __restrict__ z_old,
                       const float* __restrict__ x) {
    int bid = blockIdx.x, t = threadIdx.x;
    if (bid < HO) {
        int p = bid;
        int h = p / Oo, o = p % Oo;
        int i = t;
        const float* src = (i < Mm) ? &z_old[(o * Mm + i) * Dd] : &z[(o * Mm + (i - Mm)) * Dd];
        float s = 0.0f;
#pragma unroll
        for (int d = 0; d < Dd; d++) {
            float v = src[d] * g_invls[h][d];
            g_Zs[p][i][d] = v;
            s += v * v;
        }
        g_zn[p][i] = s;
    } else {
        int g = (bid - HO) * 256 + t;
        if (g >= Hh * Bb) return;
        int h = g / Bb, b = g % Bb;
        float s = 0.0f;
#pragma unroll
        for (int d = 0; d < Dd; d++) {
            float v = x[b * Dd + d] * g_invls[h][d];
            g_Xs[h][b][d] = v;
            s += v * v;
        }
        g_xn[h][b] = s;
    }
}

// ---------------- k_early: kuu2 (0..2047) U covTL (2048..2175) ----------------
__global__ __launch_bounds__(256) void k_early(const float* __restrict__ L_old) {
    __shared__ __align__(16) float sb[4608];
    int bid = blockIdx.x, t = threadIdx.x;

    if (bid < 2048) {
        float* zn = sb;
        int p = bid >> 4, rc = bid & 15;
        float myz[Dd];
#pragma unroll
        for (int d = 0; d < Dd; d++) myz[d] = g_Zs[p][t][d];
        zn[t] = g_zn[p][t];
        __syncthreads();
        float sf2 = g_sf2[p / Oo];
#pragma unroll 2
        for (int e = 0; e < 16; e++) {
            int row = rc * 16 + e;
            float dot = 0.0f;
#pragma unroll
            for (int d = 0; d < Dd; d++) dot += g_Zs[p][row][d] * myz[d];
            float d2 = fmaxf(zn[row] + zn[t] - 2.0f * dot, 0.0f);
            g_kuu2[p][row][t] = sf2 * __expf(-0.5f * d2);
        }
    } else {
        // cov TL = L_old @ L_old^T
        float (*Ta)[129] = (float (*)[129])sb;
        int p = bid - 2048, o = p % Oo;
        int tx = t & 15, ty = t >> 4;
        float acc[8][8];
#pragma unroll
        for (int m = 0; m < 8; m++)
#pragma unroll
            for (int n = 0; n < 8; n++) acc[m][n] = 0.0f;
        for (int kc = 0; kc < Mm; kc += 16) {
            for (int e = t; e < 2048; e += 256) {
                int i = e >> 4, c = e & 15;
                Ta[c][i] = L_old[(o * Mm + i) * Mm + kc + c];
            }
            __syncthreads();
#pragma unroll
            for (int kk = 0; kk < 16; kk++) {
                float a[8], b[8];
#pragma unroll
                for (int m = 0; m < 8; m++) a[m] = Ta[kk][ty + 16 * m];
#pragma unroll
                for (int n = 0; n < 8; n++) b[n] = Ta[kk][tx + 16 * n];
#pragma unroll
                for (int m = 0; m < 8; m++)
#pragma unroll
                    for (int n = 0; n < 8; n++) acc[m][n] += a[m] * b[n];
            }
            __syncthreads();
        }
#pragma unroll
        for (int m = 0; m < 8; m++)
#pragma unroll
            for (int n = 0; n < 8; n++) g_cov[p][ty + 16 * m][tx + 16 * n] = acc[m][n];
    }
}

// ---------------- stage A lite: chol + trtri + W11/Wt + yv only ----------------
// dyn smem: Ls 16512 | dinv 128 | mbuf 128 = 16768 fl = 67072 B
__global__ __launch_bounds__(512, 1) void k_stageA(const float* __restrict__ m_old) {
    extern __shared__ float sm[];
    float* Ls   = sm;
    float* dinv = sm + 16512;
    float* mbuf = sm + 16640;
    int p = blockIdx.x, o = p % Oo, t = threadIdx.x;

    for (int e = t; e < Mm * Mm; e += 512) {
        int i = e >> 7, j = e & 127;
        float v = g_kuu2[p][i][j];
        if (i == j) v += JIT;
        Ls[i * LDA + j] = v;
    }
    if (t < 128) mbuf[t] = m_old[o * Mm + t];
    __syncthreads();

    chol128(Ls, dinv, t);
    trtri128_blocked(Ls, dinv, t);   // Ls = W11 dense (upper zeros)

    for (int e = t; e < Mm * Mm; e += 512) {
        int i = e >> 7, k = e & 127;
        float v = Ls[i * LDA + k];
        g_W11[p][i][k] = v;
        g_Wt[p][k][i]  = v;
    }

    if (t < 128) {
        float s = 0.0f;
        for (int k = 0; k <= t; k++) s += Ls[t * LDA + k] * mbuf[k];
        g_yv[p][t] = s;
        g_vm[p][t] = s;
        g_mj[p][t] = mbuf[t];
    }
}

// ---------------- k_G1: X1 = W11@kuf (v=0), X2 = W11@L_old (v=1) ----------------
__global__ __launch_bounds__(256) void k_G1(const float* __restrict__ L_old) {
    __shared__ __align__(16) float sb[4608];
    float (*Tw)[129] = (float (*)[129])sb;
    float (*Tb)[129] = (float (*)[129])(sb + 2064);
    int bid = blockIdx.x, t = threadIdx.x;
    int v = bid >> 7, p = bid & 127, o = p % Oo;
    int tx = t & 15, ty = t >> 4;
    float acc[8][8];
#pragma unroll
    for (int m = 0; m < 8; m++)
#pragma unroll
        for (int n = 0; n < 8; n++) acc[m][n] = 0.0f;

    for (int kc = 0; kc < Mm; kc += 16) {
        for (int e = t; e < 2048; e += 256) {
            int i = e >> 4, c = e & 15;
            Tw[c][i] = g_W11[p][i][kc + c];
        }
        for (int e = t; e < 2048; e += 256) {
            int kk = e >> 7, q = e & 127;
            Tb[kk][q] = (v == 0) ? g_kuu2[p][kc + kk][Mm + q]
                                 : L_old[(o * Mm + kc + kk) * Mm + q];
        }
        __syncthreads();
#pragma unroll
        for (int kk = 0; kk < 16; kk++) {
            float a[8], b[8];
#pragma unroll
            for (int m = 0; m < 8; m++) a[m] = Tw[kk][ty + 16 * m];
#pragma unroll
            for (int n = 0; n < 8; n++) b[n] = Tb[kk][tx + 16 * n];
#pragma unroll
            for (int m = 0; m < 8; m++)
#pragma unroll
                for (int n = 0; n < 8; n++) acc[m][n] += a[m] * b[n];
        }
        __syncthreads();
    }
    if (v == 0) {
#pragma unroll
        for (int m = 0; m < 8; m++)
#pragma unroll
            for (int n = 0; n < 8; n++) g_X1[p][ty + 16 * m][tx + 16 * n] = acc[m][n];
    } else {
#pragma unroll
        for (int m = 0; m < 8; m++)
#pragma unroll
            for (int n = 0; n < 8; n++) g_X2[p][ty + 16 * m][tx + 16 * n] = acc[m][n];
    }
}

// ---------------- k_G2: kx (0..1023) U {AtX, schur, T1, m_joint} (1024..1535) ----------------
__global__ __launch_bounds__(256) void k_G2(const float* __restrict__ u_mean) {
    __shared__ __align__(16) float sb[4608];
    int bid = blockIdx.x, t = threadIdx.x;

    if (bid < 1024) {
        // ===== kx =====
        float (*zs)[Dd + 1] = (float (*)[Dd + 1])sb;
        float* zn = sb + 4352;
        int p = bid >> 3, b0 = (bid & 7) * 128;
        int h = p / Oo;
        for (int e = t; e < M2 * Dd; e += 256) {
            int i = e >> 4, d = e & 15;
            zs[i][d] = g_Zs[p][i][d];
        }
        zn[t] = g_zn[p][t];
        __syncthreads();
        int bl = t & 127, half = t >> 7;
        float xr[Dd];
#pragma unroll
        for (int d = 0; d < Dd; d++) xr[d] = g_Xs[h][b0 + bl][d];
        float xnn = g_xn[h][b0 + bl];
        float sf2 = g_sf2[h];
        for (int ii = 0; ii < 128; ii++) {
            int i = half * 128 + ii;
            float dot = 0.0f;
#pragma unroll
            for (int d = 0; d < Dd; d++) dot += zs[i][d] * xr[d];
            float d2 = fmaxf(zn[i] + xnn - 2.0f * dot, 0.0f);
            g_kx[p][i][b0 + bl] = sf2 * __expf(-0.5f * d2);
        }
        return;
    }

    int idx = bid - 1024;
    int v = idx & 3, p = idx >> 2, o = p % Oo;
    int tx = t & 15, ty = t >> 4;

    if (v == 3) {
        // m_joint second half: mj[Mm+t] = X1^T yv + u_mean
        if (t < 128) {
            float s = 0.0f;
            for (int i = 0; i < Mm; i++) s += g_X1[p][i][t] * g_yv[p][i];
            g_mj[p][Mm + t] = s + u_mean[o * Mm + t];
        }
        return;
    }

    float (*Ta)[129] = (float (*)[129])sb;
    float (*Tb)[129] = (float (*)[129])(sb + 2064);
    float acc[8][8];
#pragma unroll
    for (int m = 0; m < 8; m++)
#pragma unroll
        for (int n = 0; n < 8; n++) acc[m][n] = 0.0f;

    for (int kc = 0; kc < Mm; kc += 16) {
        if (v == 0) {
            for (int e = t; e < 2048; e += 256) {
                int kk = e >> 7, q = e & 127;
                Ta[kk][q] = g_X2[p][kc + kk][q];
                Tb[kk][q] = g_X1[p][kc + kk][q];
            }
        } else if (v == 1) {
            for (int e = t; e < 2048; e += 256) {
                int kk = e >> 7, q = e & 127;
                Ta[kk][q] = g_X1[p][kc + kk][q];
            }
        } else {
            for (int e = t; e < 2048; e += 256) {
                int kk = e >> 7, q = e & 127;
                Ta[kk][q] = g_X1[p][kc + kk][q];
                Tb[kk][q] = g_W11[p][kc + kk][q];
            }
        }
        __syncthreads();
        if (v == 0) {
            // AtX[j][k] = sum_i X2[i][j] X1[i][k]
#pragma unroll
            for (int kk = 0; kk < 16; kk++) {
                float a[8], b[8];
#pragma unroll
                for (int m = 0; m < 8; m++) a[m] = Ta[kk][ty + 16 * m];
#pragma unroll
                for (int n = 0; n < 8; n++) b[n] = Tb[kk][tx + 16 * n];
#pragma unroll
                for (int m = 0; m < 8; m++)
#pragma unroll
                    for (int n = 0; n < 8; n++) acc[m][n] += a[m] * b[n];
            }
        } else if (v == 1) {
            // X1^T X1
#pragma unroll
            for (int kk = 0; kk < 16; kk++) {
                float a[8], b[8];
#pragma unroll
                for (int m = 0; m < 8; m++) a[m] = Ta[kk][ty + 16 * m];
#pragma unroll
                for (int n = 0; n < 8; n++) b[n] = Ta[kk][tx + 16 * n];
#pragma unroll
                for (int m = 0; m < 8; m++)
#pragma unroll
                    for (int n = 0; n < 8; n++) acc[m][n] += a[m] * b[n];
            }
        } else {
            // T1[c][j] = sum_i X1[i][c] W11[i][j]
#pragma unroll
            for (int kk = 0; kk < 16; kk++) {
                float a[8], b[8];
#pragma unroll
                for (int m = 0; m < 8; m++) a[m] = Ta[kk][ty + 16 * m];
#pragma unroll
                for (int n = 0; n < 8; n++) b[n] = Tb[kk][tx + 16 * n];
#pragma unroll
                for (int m = 0; m < 8; m++)
#pragma unroll
                    for (int n = 0; n < 8; n++) acc[m][n] += a[m] * b[n];
            }
        }
        __syncthreads();
    }

    if (v == 0) {
#pragma unroll
        for (int m = 0; m < 8; m++)
#pragma unroll
            for (int n = 0; n < 8; n++) g_AtX[p][ty + 16 * m][tx + 16 * n] = acc[m][n];
    } else if (v == 1) {
#pragma unroll
        for (int m = 0; m < 8; m++)
#pragma unroll
            for (int n = 0; n < 8; n++) {
                int i = ty + 16 * m, j = tx + 16 * n;
                float val = g_kuu2[p][Mm + i][Mm + j] - acc[m][n];
                if (i == j) val += JIT;
                g_schur[p][i][j] = val;
            }
    } else {
#pragma unroll
        for (int m = 0; m < 8; m++)
#pragma unroll
            for (int n = 0; n < 8; n++) g_T1[p][ty + 16 * m][tx + 16 * n] = acc[m][n];
    }
}

// ---------------- k_G3: covBL (v=0), covBR (v=1) ----------------
__global__ __launch_bounds__(256) void k_G3(const float* __restrict__ L_old,
                                            const float* __restrict__ u_tril_vec) {
    __shared__ __align__(16) float sb[4608];
    float (*Ta)[129] = (float (*)[129])sb;
    float (*Tb)[129] = (float (*)[129])(sb + 2064);
    int bid = blockIdx.x, t = threadIdx.x;
    int v = bid >> 7, p = bid & 127, o = p % Oo;
    int tx = t & 15, ty = t >> 4;
    float acc[8][8];
#pragma unroll
    for (int m = 0; m < 8; m++)
#pragma unroll
        for (int n = 0; n < 8; n++) acc[m][n] = 0.0f;

    for (int kc = 0; kc < Mm; kc += 16) {
        if (v == 0) {
            for (int e = t; e < 2048; e += 256) {
                int i = e >> 4, c = e & 15;
                Ta[c][i] = L_old[(o * Mm + i) * Mm + kc + c];
            }
        } else {
            for (int e = t; e < 2048; e += 256) {
                int i = e >> 4, c = e & 15;
                int k = kc + c;
                Ta[c][i] = (k <= i) ? u_tril_vec[o * 8256 + (i * (i + 1)) / 2 + k] : 0.0f;
            }
        }
        for (int e = t; e < 2048; e += 256) {
            int j = e & 127, kk = e >> 7;
            Tb[kk][j] = g_AtX[p][kc + kk][j];
        }
        __syncthreads();
        if (v == 0) {
            // covBL[Mm+j][i] = sum_k AtX[k][j] L_old[i][k]
#pragma unroll
            for (int kk = 0; kk < 16; kk++) {
                float a[8], b[8];
#pragma unroll
                for (int m = 0; m < 8; m++) a[m] = Tb[kk][ty + 16 * m];
#pragma unroll
                for (int n = 0; n < 8; n++) b[n] = Ta[kk][tx + 16 * n];
#pragma unroll
                for (int m = 0; m < 8; m++)
#pragma unroll
                    for (int n = 0; n < 8; n++) acc[m][n] += a[m] * b[n];
            }
        } else {
            // covBR = U U^T + AtX^T AtX
#pragma unroll
            for (int kk = 0; kk < 16; kk++) {
                float a[8], b[8], c2[8], d2[8];
#pragma unroll
                for (int m = 0; m < 8; m++) { a[m] = Ta[kk][ty + 16 * m]; c2[m] = Tb[kk][ty + 16 * m]; }
#pragma unroll
                for (int n = 0; n < 8; n++) { b[n] = Ta[kk][tx + 16 * n]; d2[n] = Tb[kk][tx + 16 * n]; }
#pragma unroll
                for (int m = 0; m < 8; m++)
#pragma unroll
                    for (int n = 0; n < 8; n++) acc[m][n] += a[m] * b[n] + c2[m] * d2[n];
            }
        }
        __syncthreads();
    }

    int c0 = (v == 1) ? Mm : 0;
#pragma unroll
    for (int m = 0; m < 8; m++)
#pragma unroll
        for (int n = 0; n < 8; n++) g_cov[p][Mm + ty + 16 * m][c0 + tx + 16 * n] = acc[m][n];
}

// ---------------- k_BB: fused B1f (blocks 0..127) + B2n' (blocks 128..255) ----------------
__global__ __launch_bounds__(256, 2) void k_BB() {
    extern __shared__ float sm[];
    int t = threadIdx.x;
    int tx = t & 15, ty = t >> 4;

    if (blockIdx.x < HO) {
        float* S    = sm;
        float* stg  = sm + 16512;
        float* dinv = sm + 18560;
        float* mjs  = sm + 18688;
        float* vbuf = sm + 18944;
        int p = blockIdx.x;

        for (int e = t; e < Mm * Mm; e += 256) {
            int i = e >> 7, j = e & 127;
            S[i * LDA + j] = g_schur[p][i][j];
        }
        mjs[t] = g_mj[p][t];
        __syncthreads();
        chol128(S, dinv, t);
        trtri128_blocked(S, dinv, t);

        for (int e = t; e < Mm * Mm; e += 256) {
            int k = e >> 7, i = e & 127;
            g_Wt[p][Mm + k][Mm + i] = S[i * LDA + k];
        }

        float acc[8][8];
#pragma unroll
        for (int m = 0; m < 8; m++)
#pragma unroll
            for (int n = 0; n < 8; n++) acc[m][n] = 0.0f;
        for (int kc = 0; kc < Mm; kc += 16) {
            for (int e = t; e < 2048; e += 256) {
                int kk = e >> 7, q = e & 127;
                stg[kk * 128 + q] = g_T1[p][kc + kk][q];
            }
            __syncthreads();
#pragma unroll
            for (int kk = 0; kk < 16; kk++) {
                float a[8], b[8];
#pragma unroll
                for (int m = 0; m < 8; m++) a[m] = S[(ty + 16 * m) * LDA + kc + kk];
#pragma unroll
                for (int n = 0; n < 8; n++) b[n] = stg[kk * 128 + tx + 16 * n];
#pragma unroll
                for (int m = 0; m < 8; m++)
#pragma unroll
                    for (int n = 0; n < 8; n++) acc[m][n] -= a[m] * b[n];
            }
            __syncthreads();
        }
#pragma unroll
        for (int m = 0; m < 8; m++) {
            float pm = 0.0f;
#pragma unroll
            for (int n = 0; n < 8; n++) {
                int r = ty + 16 * m, j = tx + 16 * n;
                g_Wt[p][j][Mm + r] = acc[m][n];
                pm += acc[m][n] * mjs[j];
            }
            vbuf[(ty + 16 * m) * 16 + tx] = pm;
        }
        __syncthreads();
        if (t < 128) {
            float s = 0.0f;
#pragma unroll
            for (int x2 = 0; x2 < 16; x2++) s += vbuf[t * 16 + x2];
            for (int j = 0; j < Mm; j++) s += S[t * LDA + j] * mjs[Mm + j];
            g_vm[p][Mm + t] = s;
        }
    } else {
        float* C    = sm;
        float (*Ta)[129] = (float (*)[129])(sm + 16512);
        float* dinv = sm + 18576;
        int p = blockIdx.x - HO;

        for (int e = t; e < Mm * Mm; e += 256) {
            int i = e >> 7, j = e & 127;
            float v = g_cov[p][i][j];
            if (i == j) v += JIT;
            C[i * LDA + j] = v;
        }
        __syncthreads();
        chol128(C, dinv, t);
        for (int e = t; e < Mm * Mm; e += 256) {
            int i = e >> 7, k = e & 127;
            g_L11p[p][i][k] = (k <= i) ? C[i * LDA + k] : 0.0f;
        }
        __syncthreads();
        trtri128_blocked(C, dinv, t);

        {
            float acc[8][8];
#pragma unroll
            for (int m = 0; m < 8; m++)
#pragma unroll
                for (int n = 0; n < 8; n++) acc[m][n] = 0.0f;
            for (int kc = 0; kc < Mm; kc += 16) {
                for (int e = t; e < 2048; e += 256) {
                    int r = e >> 4, c = e & 15;
                    Ta[c][r] = g_cov[p][Mm + r][kc + c];
                }
                __syncthreads();
#pragma unroll
                for (int kk = 0; kk < 16; kk++) {
                    float a[8], b[8];
#pragma unroll
                    for (int m = 0; m < 8; m++) a[m] = Ta[kk][ty + 16 * m];
#pragma unroll
                    for (int n = 0; n < 8; n++) b[n] = C[(tx + 16 * n) * LDA + kc + kk];
#pragma unroll
                    for (int m = 0; m < 8; m++)
#pragma unroll
                        for (int n = 0; n < 8; n++) acc[m][n] += a[m] * b[n];
                }
                __syncthreads();
            }
#pragma unroll
            for (int m = 0; m < 8; m++)
#pragma unroll
                for (int n = 0; n < 8; n++) g_L21p[p][ty + 16 * m][tx + 16 * n] = acc[m][n];
        }
        __syncthreads();

        {
            float acc[8][8];
#pragma unroll
            for (int m = 0; m < 8; m++)
#pragma unroll
                for (int n = 0; n < 8; n++) acc[m][n] = 0.0f;
            for (int kc = 0; kc < Mm; kc += 16) {
                for (int e = t; e < 2048; e += 256) {
                    int r = e >> 4, c = e & 15;
                    Ta[c][r] = g_L21p[p][r][kc + c];
                }
                __syncthreads();
#pragma unroll
                for (int kk = 0; kk < 16; kk++) {
                    float a[8], b[8];
#pragma unroll
                    for (int m = 0; m < 8; m++) a[m] = Ta[kk][ty + 16 * m];
#pragma unroll
                    for (int n = 0; n < 8; n++) b[n] = Ta[kk][tx + 16 * n];
#pragma unroll
                    for (int m = 0; m < 8; m++)
#pragma unroll
                        for (int n = 0; n < 8; n++) acc[m][n] += a[m] * b[n];
                }
                __syncthreads();
            }
#pragma unroll
            for (int m = 0; m < 8; m++)
#pragma unroll
                for (int n = 0; n < 8; n++) {
                    int i = ty + 16 * m, j = tx + 16 * n;
                    float v = g_cov[p][Mm + i][Mm + j] - acc[m][n];
                    if (i == j) v += JIT;
                    C[i * LDA + j] = v;
                }
        }
        __syncthreads();
        chol128(C, dinv, t);
        for (int e = t; e < Mm * Mm; e += 256) {
            int i = e >> 7, k = e & 127;
            g_L22p[p][i][k] = (k <= i) ? C[i * LDA + k] : 0.0f;
        }
    }
}

// ---------------- k_RA: gemmA (blocks 0..2047) U k_R (blocks 2048..2431) ----------------
__global__ __launch_bounds__(256) void k_RA() {
    __shared__ __align__(16) float sb[6272];
    int bid = blockIdx.x, t = threadIdx.x;

    if (bid < 2048) {
        float* As = sb;
        float* Bs = sb + 2048;
        float* vs = sb + 4096;
        float* red = sb + 4224;
        int b0 = (bid & 7) * 128, by = (bid >> 3) & 1, p = bid >> 4;
        int i0 = by * 128;
        int tx = t % 16, ty = t / 16;
        if (t < 128) vs[t] = g_vm[p][i0 + t];
        unsigned long long acc[8][4];
#pragma unroll
        for (int m = 0; m < 8; m++)
#pragma unroll
            for (int n = 0; n < 4; n++) acc[m][n] = 0ULL;

        int kmax = i0 + 128;
        for (int kc = 0; kc < kmax; kc += 16) {
#pragma unroll
            for (int e = 0; e < 2; e++) {
                int q = t + e * 256;
                int kk = q >> 5, c4 = q & 31;
                *(float4*)&As[kk * 128 + c4 * 4] = *(const float4*)&g_Wt[p][kc + kk][i0 + c4 * 4];
                *(float4*)&Bs[kk * 128 + c4 * 4] = *(const float4*)&g_kx[p][kc + kk][b0 + c4 * 4];
            }
            __syncthreads();
#pragma unroll
            for (int kk = 0; kk < 16; kk++) {
                float4 a0 = *(const float4*)&As[kk * 128 + ty * 8];
                float4 a1 = *(const float4*)&As[kk * 128 + ty * 8 + 4];
                float4 q0 = *(const float4*)&Bs[kk * 128 + tx * 8];
                float4 q1 = *(const float4*)&Bs[kk * 128 + tx * 8 + 4];
                unsigned long long bp[4] = { pk2(q0.x, q0.y), pk2(q0.z, q0.w), pk2(q1.x, q1.y), pk2(q1.z, q1.w) };
                float am[8] = { a0.x, a0.y, a0.z, a0.w, a1.x, a1.y, a1.z, a1.w };
#pragma unroll
                for (int m = 0; m < 8; m++) {
                    unsigned long long ad = pk2(am[m], am[m]);
#pragma unroll
                    for (int n = 0; n < 4; n++) acc[m][n] = ffma2(ad, bp[n], acc[m][n]);
                }
            }
            __syncthreads();
        }
        float av[8][8];
#pragma unroll
        for (int m = 0; m < 8; m++) {
#pragma unroll
            for (int n = 0; n < 4; n++) {
                float2 v = upk2(acc[m][n]);
                av[m][n * 2] = v.x; av[m][n * 2 + 1] = v.y;
            }
            *(float4*)&g_a[p][i0 + ty * 8 + m][b0 + tx * 8]     = make_float4(av[m][0], av[m][1], av[m][2], av[m][3]);
            *(float4*)&g_a[p][i0 + ty * 8 + m][b0 + tx * 8 + 4] = make_float4(av[m][4], av[m][5], av[m][6], av[m][7]);
        }
#pragma unroll
        for (int n = 0; n < 8; n++) {
            float s = 0.0f;
#pragma unroll
            for (int m = 0; m < 8; m++) s += av[m][n] * av[m][n];
            red[ty * 128 + tx * 8 + n] = s;
        }
        __syncthreads();
        if (t < 128) {
            float s = 0.0f;
#pragma unroll
            for (int y = 0; y < 16; y++) s += red[y * 128 + t];
            g_d1p[by][p][b0 + t] = s;
        }
        __syncthreads();
#pragma unroll
        for (int n = 0; n < 8; n++) {
            float s = 0.0f;
#pragma unroll
            for (int m = 0; m < 8; m++) s += vs[ty * 8 + m] * av[m][n];
            red[ty * 128 + tx * 8 + n] = s;
        }
        __syncthreads();
        if (t < 128) {
            float s = 0.0f;
#pragma unroll
            for (int y = 0; y < 16; y++) s += red[y * 128 + t];
            g_mup[by][p][b0 + t] = s;
        }
    } else {
        float* As = sb;
        float* Bs = sb + 2048;
        int r = bid - 2048;
        int v = r / HO, p = r % HO;
        int tx = t & 15, ty = t >> 4;
        float acc[8][8];
#pragma unroll
        for (int m = 0; m < 8; m++)
#pragma unroll
            for (int n = 0; n < 8; n++) acc[m][n] = 0.0f;

        int kTot = (v == 1) ? M2 : Mm;
        for (int kc = 0; kc < kTot; kc += 16) {
            for (int e = t; e < 2048; e += 256) {
                int kk = e >> 7, q = e & 127;
                int kg = kc + kk;
                float av, bv;
                if (v == 0) { av = g_Wt[p][kg][q];            bv = g_L11p[p][kg][q]; }
                else if (v == 1) {
                    av = g_Wt[p][kg][Mm + q];
                    bv = (kg < Mm) ? g_L11p[p][kg][q] : g_L21p[p][kg - Mm][q];
                }
                else { av = g_Wt[p][Mm + kg][Mm + q];         bv = g_L22p[p][kg][q]; }
                As[kk * 128 + q] = av;
                Bs[kk * 128 + q] = bv;
            }
            __syncthreads();
#pragma unroll
            for (int kk = 0; kk < 16; kk++) {
                float4 a0 = *(const float4*)&As[kk * 128 + ty * 8];
                float4 a1 = *(const float4*)&As[kk * 128 + ty * 8 + 4];
                float4 b0 = *(const float4*)&Bs[kk * 128 + tx * 8];
                float4 b1 = *(const float4*)&Bs[kk * 128 + tx * 8 + 4];
                float am[8] = { a0.x, a0.y, a0.z, a0.w, a1.x, a1.y, a1.z, a1.w };
                float bn[8] = { b0.x, b0.y, b0.z, b0.w, b1.x, b1.y, b1.z, b1.w };
#pragma unroll
                for (int m = 0; m < 8; m++)
#pragma unroll
                    for (int n = 0; n < 8; n++) acc[m][n] += am[m] * bn[n];
            }
            __syncthreads();
        }
        int r0 = (v == 0) ? 0 : Mm;
        int c0 = (v == 2) ? Mm : 0;
#pragma unroll
        for (int m = 0; m < 8; m++) {
            *(float4*)&g_R[p][r0 + ty * 8 + m][c0 + tx * 8]     = make_float4(acc[m][0], acc[m][1], acc[m][2], acc[m][3]);
            *(float4*)&g_R[p][r0 + ty * 8 + m][c0 + tx * 8 + 4] = make_float4(acc[m][4], acc[m][5], acc[m][6], acc[m][7]);
        }
    }
}

// ---------------- gemmH: h = R^T @ a, d2 partials (FFMA2) ----------------
__global__ __launch_bounds__(256) void k_gemmH() {
    __shared__ float As[16][128];
    __shared__ float Bs[16][128];
    __shared__ float red[16][128];
    int p = blockIdx.z;
    int j0 = blockIdx.y * 128, b0 = blockIdx.x * 128;
    int t = threadIdx.x, tx = t % 16, ty = t / 16;
    unsigned long long acc[8][4];
#pragma unroll
    for (int m = 0; m < 8; m++)
#pragma unroll
        for (int n = 0; n < 4; n++) acc[m][n] = 0ULL;

    for (int kc = j0; kc < M2; kc += 16) {
#pragma unroll
        for (int e = 0; e < 2; e++) {
            int q = t + e * 256;
            int kk = q >> 5, c4 = q & 31;
            *(float4*)&As[kk][c4 * 4] = *(const float4*)&g_R[p][kc + kk][j0 + c4 * 4];
            *(float4*)&Bs[kk][c4 * 4] = *(const float4*)&g_a[p][kc + kk][b0 + c4 * 4];
        }
        __syncthreads();
#pragma unroll
        for (int kk = 0; kk < 16; kk++) {
            float4 a0 = *(const float4*)&As[kk][ty * 8];
            float4 a1 = *(const float4*)&As[kk][ty * 8 + 4];
            float4 q0 = *(const float4*)&Bs[kk][tx * 8];
            float4 q1 = *(const float4*)&Bs[kk][tx * 8 + 4];
            unsigned long long bp[4] = { pk2(q0.x, q0.y), pk2(q0.z, q0.w), pk2(q1.x, q1.y), pk2(q1.z, q1.w) };
            float am[8] = { a0.x, a0.y, a0.z, a0.w, a1.x, a1.y, a1.z, a1.w };
#pragma unroll
            for (int m = 0; m < 8; m++) {
                unsigned long long ad = pk2(am[m], am[m]);
#pragma unroll
                for (int n = 0; n < 4; n++) acc[m][n] = ffma2(ad, bp[n], acc[m][n]);
            }
        }
        __syncthreads();
    }
#pragma unroll
    for (int n = 0; n < 8; n++) {
        float s = 0.0f;
#pragma unroll
        for (int m = 0; m < 8; m++) {
            float2 v = upk2(acc[m][n / 2]);
            float h = (n & 1) ? v.y : v.x;
            s += h * h;
        }
        red[ty][tx * 8 + n] = s;
    }
    __syncthreads();
    if (t < 128) {
        float s = 0.0f;
#pragma unroll
        for (int y = 0; y < 16; y++) s += red[y][t];
        g_d2p[blockIdx.y][p][b0 + t] = s;
    }
}

// ---------------- final ----------------
__global__ void k_final(float* __restrict__ out) {
    int idx = blockIdx.x * 256 + threadIdx.x;
    if (idx >= HOB) return;
    int p = idx / Bb, b = idx % Bb;
    out[idx] = g_mup[0][p][b] + g_mup[1][p][b];
    out[HOB + idx] = g_sf2[p / Oo] - (g_d1p[0][p][b] + g_d1p[1][p][b]) + (g_d2p[0][p][b] + g_d2p[1][p][b]);
}

extern "C" void kernel_launch(void* const* d_in, const int* in_sizes, int n_in,
                              void* d_out, int out_size) {
    const float* x          = (const float*)d_in[0];
    const float* z          = (const float*)d_in[1];
    const float* u_mean     = (const float*)d_in[2];
    const float* u_tril_vec = (const float*)d_in[3];
    const float* m_old      = (const float*)d_in[4];
    const float* L_old      = (const float*)d_in[5];
    const float* z_old      = (const float*)d_in[6];
    const float* theta      = (const float*)d_in[7];
    float* out = (float*)d_out;

    static bool init_done = false;
    if (!init_done) {
        cudaFuncSetAttribute(k_stageA, cudaFuncAttributeMaxDynamicSharedMemorySize, 67072);
        cudaFuncSetAttribute(k_BB,     cudaFuncAttributeMaxDynamicSharedMemorySize, 83968);
        init_done = true;
    }

    // single stream; stageA stays at host-launch slot 3 for the profiler
    k_prep_theta<<<1, 128>>>(theta);
    k_prep<<<144, 256>>>(z, z_old, x);
    k_early<<<2176, 256>>>(L_old);
    k_stageA<<<HO, 512, 67072>>>(m_old);
    k_G1<<<256, 256>>>(L_old);
    k_G2<<<1536, 256>>>(u_mean);
    k_G3<<<256, 256>>>(L_old, u_tril_vec);
    k_BB<<<256, 256, 83968>>>();
    k_RA<<<2432, 256>>>();
    k_gemmH<<<dim3(8, 2, HO), 256>>>();
    k_final<<<512, 256>>>(out);
}

// round 17
// speedup vs baseline: 1.0839x; 1.0839x over previous
#include <cuda_runtime.h>

#define Hh 4
#define Oo 32
#define Mm 128
#define M2 256
#define Dd 16
#define Bb 1024
#define HO 128
#define HOB (HO*Bb)
#define JIT 1e-4f
#define LDA 129

// ---------------- f32x2 helpers ----------------
__device__ __forceinline__ unsigned long long pk2(float lo, float hi) {
    unsigned long long r;
    asm("mov.b64 %0, {%1, %2};" : "=l"(r) : "f"(lo), "f"(hi));
    return r;
}
__device__ __forceinline__ float2 upk2(unsigned long long v) {
    float2 r;
    asm("mov.b64 {%0, %1}, %2;" : "=f"(r.x), "=f"(r.y) : "l"(v));
    return r;
}
__device__ __forceinline__ unsigned long long ffma2(unsigned long long a, unsigned long long b, unsigned long long c) {
    unsigned long long d;
    asm("fma.rn.f32x2 %0, %1, %2, %3;" : "=l"(d) : "l"(a), "l"(b), "l"(c));
    return d;
}

// ---------------- device scratch ----------------
__device__ float g_sf2[Hh];
__device__ float g_invls[Hh][Dd];
__device__ float g_Xs[Hh][Bb][Dd];
__device__ float g_xn[Hh][Bb];
__device__ float g_Zs[HO][M2][Dd];
__device__ float g_zn[HO][M2];
__device__ float g_kuu2[HO][M2][M2];
__device__ float g_cov[HO][M2][M2];
__device__ float g_Wt[HO][M2][M2];     // Wt[k][i] = Linv256[i][k]
__device__ float g_R[HO][M2][M2];
__device__ float g_vm[HO][M2];
__device__ float g_mj[HO][M2];
__device__ float g_kx[HO][M2][Bb];
__device__ float g_a[HO][M2][Bb];
__device__ float g_X1[HO][Mm][Mm];
__device__ float g_W11[HO][Mm][Mm];
__device__ float g_T1[HO][Mm][Mm];
__device__ float g_AtX[HO][Mm][Mm];
__device__ float g_schur[HO][Mm][Mm];
__device__ float g_L11p[HO][Mm][Mm];
__device__ float g_L21p[HO][Mm][Mm];
__device__ float g_L22p[HO][Mm][Mm];
__device__ float g_d1p[2][HO][Bb];
__device__ float g_d2p[2][HO][Bb];
__device__ float g_mup[2][HO][Bb];

// ---------------- blocked right-looking Cholesky (panel 16) ----------------
__device__ void chol128(float* Ls, float* dinv, int t) {
    const int NB = 16;
    for (int pb = 0; pb < Mm; pb += NB) {
        // panel factorization: columns pb..pb+15
        for (int jj = 0; jj < NB; jj++) {
            int j = pb + jj;
            if (t == 0) {
                float s = 0.0f;
                for (int k = pb; k < j; k++) { float v = Ls[j * LDA + k]; s += v * v; }
                float d = sqrtf(Ls[j * LDA + j] - s);
                Ls[j * LDA + j] = d;
                dinv[j] = 1.0f / d;
            }
            __syncthreads();
            int i = j + 1 + t;
            if (i < Mm) {
                float s = 0.0f;
                for (int k = pb; k < j; k++) s += Ls[i * LDA + k] * Ls[j * LDA + k];
                Ls[i * LDA + j] = (Ls[i * LDA + j] - s) * dinv[j];
            }
            __syncthreads();
        }
        // trailing rank-16 update on lower triangle of remaining block
        int pe = pb + NB;
        if (pe < Mm) {
            int rem = Mm - pe;
            for (int e = t; e < rem * rem; e += blockDim.x) {
                int r = pe + e / rem, c = pe + e % rem;
                if (c <= r) {
                    float s0 = 0, s1 = 0, s2 = 0, s3 = 0;
#pragma unroll
                    for (int k = 0; k < NB; k += 4) {
                        s0 += Ls[r * LDA + pb + k]     * Ls[c * LDA + pb + k];
                        s1 += Ls[r * LDA + pb + k + 1] * Ls[c * LDA + pb + k + 1];
                        s2 += Ls[r * LDA + pb + k + 2] * Ls[c * LDA + pb + k + 2];
                        s3 += Ls[r * LDA + pb + k + 3] * Ls[c * LDA + pb + k + 3];
                    }
                    Ls[r * LDA + c] -= (s0 + s1) + (s2 + s3);
                }
            }
            __syncthreads();
        }
    }
}

__device__ void trtri128_blocked(float* Ls, float* dinv, int t) {
    if (t == 0) Ls[0] = dinv[0];
    if (t == 1) Ls[64 * LDA + 64] = dinv[64];
    __syncthreads();
    for (int i = 1; i < 64; i++) {
        float v = 0.0f;
        bool actA = (t < i);
        int u = t - 128;
        bool actB = (u >= 0 && u < i);
        if (actA) {
            float s0 = 0, s1 = 0, s2 = 0, s3 = 0;
            int k = t;
            for (; k + 3 < i; k += 4) {
                s0 += Ls[i * LDA + k]     * Ls[(k)     * LDA + t];
                s1 += Ls[i * LDA + k + 1] * Ls[(k + 1) * LDA + t];
                s2 += Ls[i * LDA + k + 2] * Ls[(k + 2) * LDA + t];
                s3 += Ls[i * LDA + k + 3] * Ls[(k + 3) * LDA + t];
            }
            for (; k < i; k++) s0 += Ls[i * LDA + k] * Ls[k * LDA + t];
            v = -dinv[i] * ((s0 + s1) + (s2 + s3));
        } else if (actB) {
            const int O = 64 * LDA + 64;
            float s0 = 0, s1 = 0, s2 = 0, s3 = 0;
            int k = u;
            for (; k + 3 < i; k += 4) {
                s0 += Ls[O + i * LDA + k]     * Ls[O + (k)     * LDA + u];
                s1 += Ls[O + i * LDA + k + 1] * Ls[O + (k + 1) * LDA + u];
                s2 += Ls[O + i * LDA + k + 2] * Ls[O + (k + 2) * LDA + u];
                s3 += Ls[O + i * LDA + k + 3] * Ls[O + (k + 3) * LDA + u];
            }
            for (; k < i; k++) s0 += Ls[O + i * LDA + k] * Ls[O + k * LDA + u];
            v = -dinv[64 + i] * ((s0 + s1) + (s2 + s3));
        }
        __syncthreads();
        if (actA) Ls[i * LDA + t] = v;
        if (actB) Ls[(64 + i) * LDA + 64 + u] = v;
        if (t == 0) Ls[i * LDA + i] = dinv[i];
        if (t == 1) Ls[(64 + i) * LDA + 64 + i] = dinv[64 + i];
        __syncthreads();
    }
    for (int e = t; e < 64 * 64; e += blockDim.x) {
        int r = e >> 6, c = e & 63;
        if (c > r) { Ls[r * LDA + c] = 0.0f; Ls[(64 + r) * LDA + 64 + c] = 0.0f; }
        Ls[r * LDA + 64 + c] = 0.0f;
    }
    __syncthreads();
    int tx = t & 15, ty = (t >> 4) & 15;
    bool act = (t < 256);
    float T[4][4];
#pragma unroll
    for (int m = 0; m < 4; m++)
#pragma unroll
        for (int n = 0; n < 4; n++) T[m][n] = 0.0f;
    if (act) {
        for (int k = 0; k < 64; k++) {
            float a[4], b[4];
#pragma unroll
            for (int m = 0; m < 4; m++) a[m] = Ls[(64 + ty + 16 * m) * LDA + k];
#pragma unroll
            for (int n = 0; n < 4; n++) b[n] = Ls[k * LDA + tx + 16 * n];
#pragma unroll
            for (int m = 0; m < 4; m++)
#pragma unroll
                for (int n = 0; n < 4; n++) T[m][n] += a[m] * b[n];
        }
    }
    __syncthreads();
    if (act) {
#pragma unroll
        for (int m = 0; m < 4; m++)
#pragma unroll
            for (int n = 0; n < 4; n++) Ls[(64 + ty + 16 * m) * LDA + tx + 16 * n] = T[m][n];
    }
    __syncthreads();
#pragma unroll
    for (int m = 0; m < 4; m++)
#pragma unroll
        for (int n = 0; n < 4; n++) T[m][n] = 0.0f;
    if (act) {
        for (int k = 0; k < 64; k++) {
            float a[4], b[4];
#pragma unroll
            for (int m = 0; m < 4; m++) a[m] = Ls[(64 + ty + 16 * m) * LDA + 64 + k];
#pragma unroll
            for (int n = 0; n < 4; n++) b[n] = Ls[(64 + k) * LDA + tx + 16 * n];
#pragma unroll
            for (int m = 0; m < 4; m++)
#pragma unroll
                for (int n = 0; n < 4; n++) T[m][n] -= a[m] * b[n];
        }
    }
    __syncthreads();
    if (act) {
#pragma unroll
        for (int m = 0; m < 4; m++)
#pragma unroll
            for (int n = 0; n < 4; n++) Ls[(64 + ty + 16 * m) * LDA + tx + 16 * n] = T[m][n];
    }
    __syncthreads();
}

// ---------------- prep ----------------
__global__ void k_prep_theta(const float* __restrict__ theta) {
    int t = threadIdx.x;
    if (t < Hh * (Dd + 1)) {
        int h = t / (Dd + 1), c = t % (Dd + 1);
        float v = theta[t];
        if (c == 0) g_sf2[h] = expf(v);
        else        g_invls[h][c - 1] = expf(-v);
    }
}

__global__ void k_prep_x(const float* __restrict__ x) {
    int g = blockIdx.x * blockDim.x + threadIdx.x;
    if (g >= Hh * Bb) return;
    int h = g / Bb, b = g % Bb;
    float s = 0.0f;
#pragma unroll
    for (int d = 0; d < Dd; d++) {
        float v = x[b * Dd + d] * g_invls[h][d];
        g_Xs[h][b][d] = v;
        s += v * v;
    }
    g_xn[h][b] = s;
}

__global__ void k_prep_z(const float* __restrict__ z, const float* __restrict__ z_old) {
    int p = blockIdx.x;
    int h = p / Oo, o = p % Oo;
    int i = threadIdx.x;
    const float* src = (i < Mm) ? &z_old[(o * Mm + i) * Dd] : &z[(o * Mm + (i - Mm)) * Dd];
    float s = 0.0f;
#pragma unroll
    for (int d = 0; d < Dd; d++) {
        float v = src[d] * g_invls[h][d];
        g_Zs[p][i][d] = v;
        s += v * v;
    }
    g_zn[p][i] = s;
}

__global__ void k_kuu2() {
    __shared__ float zn[M2];
    int p = blockIdx.y, rc = blockIdx.x, t = threadIdx.x;
    float myz[Dd];
#pragma unroll
    for (int d = 0; d < Dd; d++) myz[d] = g_Zs[p][t][d];
    zn[t] = g_zn[p][t];
    __syncthreads();
    float sf2 = g_sf2[p / Oo];
#pragma unroll 2
    for (int e = 0; e < 16; e++) {
        int row = rc * 16 + e;
        float dot = 0.0f;
#pragma unroll
        for (int d = 0; d < Dd; d++) dot += g_Zs[p][row][d] * myz[d];
        float d2 = fmaxf(zn[row] + zn[t] - 2.0f * dot, 0.0f);
        g_kuu2[p][row][t] = sf2 * __expf(-0.5f * d2);
    }
}

// ---------------- stage A (512 threads; cov split out) ----------------
// dyn smem: Ls 16512 | X1 16512 | X2 16512 | stg 2048 | dinv 128 | yv 128 | mbuf 128 = 51968 fl = 207872 B
__global__ __launch_bounds__(512, 1) void k_stageA(
        const float* __restrict__ m_old, const float* __restrict__ L_old,
        const float* __restrict__ u_mean, const float* __restrict__ u_tril_vec) {
    extern __shared__ float sm[];
    float* Ls   = sm;
    float* X1   = sm + 16512;
    float* X2   = sm + 33024;
    float* stg  = sm + 49536;
    float* dinv = sm + 51584;
    float* yv   = sm + 51712;
    float* mbuf = sm + 51840;
    int p = blockIdx.x, o = p % Oo, t = threadIdx.x;
    int tx = t & 15, ty = t >> 4;   // ty 0..31

    for (int e = t; e < Mm * Mm; e += 512) {
        int i = e >> 7, j = e & 127;
        float v = g_kuu2[p][i][j];
        if (i == j) v += JIT;
        Ls[i * LDA + j] = v;
    }
    __syncthreads();

    chol128(Ls, dinv, t);
    trtri128_blocked(Ls, dinv, t);   // Ls = W11 dense (upper zeros)

    for (int e = t; e < Mm * Mm; e += 512) {
        int i = e >> 7, k = e & 127;
        g_W11[p][i][k] = Ls[i * LDA + k];
        g_Wt[p][k][i]  = Ls[i * LDA + k];
    }

    // X1 = W11 @ kuf
    {
        float acc[4][8];
#pragma unroll
        for (int m = 0; m < 4; m++)
#pragma unroll
            for (int n = 0; n < 8; n++) acc[m][n] = 0.0f;
        for (int kc = 0; kc < Mm; kc += 16) {
            for (int e = t; e < 2048; e += 512) {
                int kk = e >> 7, c = e & 127;
                stg[kk * 128 + c] = g_kuu2[p][kc + kk][Mm + c];
            }
            __syncthreads();
#pragma unroll
            for (int kk = 0; kk < 16; kk++) {
                float a[4], b[8];
#pragma unroll
                for (int m = 0; m < 4; m++) a[m] = Ls[(ty + 32 * m) * LDA + kc + kk];
#pragma unroll
                for (int n = 0; n < 8; n++) b[n] = stg[kk * 128 + tx + 16 * n];
#pragma unroll
                for (int m = 0; m < 4; m++)
#pragma unroll
                    for (int n = 0; n < 8; n++) acc[m][n] += a[m] * b[n];
            }
            __syncthreads();
        }
#pragma unroll
        for (int m = 0; m < 4; m++)
#pragma unroll
            for (int n = 0; n < 8; n++) {
                X1[(ty + 32 * m) * LDA + tx + 16 * n] = acc[m][n];
                g_X1[p][ty + 32 * m][tx + 16 * n] = acc[m][n];
            }
    }
    // X2 = W11 @ L_old
    {
        float acc[4][8];
#pragma unroll
        for (int m = 0; m < 4; m++)
#pragma unroll
            for (int n = 0; n < 8; n++) acc[m][n] = 0.0f;
        for (int kc = 0; kc < Mm; kc += 16) {
            for (int e = t; e < 2048; e += 512) {
                int kk = e >> 7, c = e & 127;
                stg[kk * 128 + c] = L_old[(o * Mm + kc + kk) * Mm + c];
            }
            __syncthreads();
#pragma unroll
            for (int kk = 0; kk < 16; kk++) {
                float a[4], b[8];
#pragma unroll
                for (int m = 0; m < 4; m++) a[m] = Ls[(ty + 32 * m) * LDA + kc + kk];
#pragma unroll
                for (int n = 0; n < 8; n++) b[n] = stg[kk * 128 + tx + 16 * n];
#pragma unroll
                for (int m = 0; m < 4; m++)
#pragma unroll
                    for (int n = 0; n < 8; n++) acc[m][n] += a[m] * b[n];
            }
            __syncthreads();
        }
#pragma unroll
        for (int m = 0; m < 4; m++)
#pragma unroll
            for (int n = 0; n < 8; n++) X2[(ty + 32 * m) * LDA + tx + 16 * n] = acc[m][n];
    }
    __syncthreads();

    // yv = W11 @ m_old
    if (t < 128) mbuf[t] = m_old[o * Mm + t];
    __syncthreads();
    if (t < 128) {
        float s = 0.0f;
        for (int k = 0; k <= t; k++) s += Ls[t * LDA + k] * mbuf[k];
        yv[t] = s;
        g_vm[p][t] = s;
    }
    __syncthreads();

    // m_joint
    if (t < 128) {
        float s = 0.0f;
        for (int i = 0; i < Mm; i++) s += X1[i * LDA + t] * yv[i];
        g_mj[p][t] = mbuf[t];
        g_mj[p][Mm + t] = s + u_mean[o * Mm + t];
    }
    __syncthreads();

    // AtX[j][k] = sum_i X2[i][j]*X1[i][k] -> persist to g_AtX
    {
        float c[4][8];
#pragma unroll
        for (int m = 0; m < 4; m++)
#pragma unroll
            for (int n = 0; n < 8; n++) c[m][n] = 0.0f;
        for (int i = 0; i < Mm; i++) {
            float a[4], b[8];
#pragma unroll
            for (int m = 0; m < 4; m++) a[m] = X2[i * LDA + ty + 32 * m];
#pragma unroll
            for (int n = 0; n < 8; n++) b[n] = X1[i * LDA + tx + 16 * n];
#pragma unroll
            for (int m = 0; m < 4; m++)
#pragma unroll
                for (int n = 0; n < 8; n++) c[m][n] += a[m] * b[n];
        }
#pragma unroll
        for (int m = 0; m < 4; m++)
#pragma unroll
            for (int n = 0; n < 8; n++) g_AtX[p][ty + 32 * m][tx + 16 * n] = c[m][n];
    }

    // schur = kuu_new + jit I - X1^T X1
    {
        float c[4][8];
#pragma unroll
        for (int m = 0; m < 4; m++)
#pragma unroll
            for (int n = 0; n < 8; n++) c[m][n] = 0.0f;
        for (int k = 0; k < Mm; k++) {
            float a[4], b[8];
#pragma unroll
            for (int m = 0; m < 4; m++) a[m] = X1[k * LDA + ty + 32 * m];
#pragma unroll
            for (int n = 0; n < 8; n++) b[n] = X1[k * LDA + tx + 16 * n];
#pragma unroll
            for (int m = 0; m < 4; m++)
#pragma unroll
                for (int n = 0; n < 8; n++) c[m][n] += a[m] * b[n];
        }
#pragma unroll
        for (int m = 0; m < 4; m++)
#pragma unroll
            for (int n = 0; n < 8; n++) {
                int i = ty + 32 * m, j = tx + 16 * n;
                float v = g_kuu2[p][Mm + i][Mm + j] - c[m][n];
                if (i == j) v += JIT;
                g_schur[p][i][j] = v;
            }
    }
}

// ---------------- k_mid: kx (blocks 0..1023) U covT1 (blocks 1024..1535) ----------------
__global__ __launch_bounds__(256) void k_mid(const float* __restrict__ L_old,
                                             const float* __restrict__ u_tril_vec) {
    __shared__ __align__(16) float sb[4608];
    int bid = blockIdx.x, t = threadIdx.x;

    if (bid < 1024) {
        // ===== kx =====
        float (*zs)[Dd + 1] = (float (*)[Dd + 1])sb;
        float* zn = sb + 4352;
        int p = bid >> 3, b0 = (bid & 7) * 128;
        int h = p / Oo;
        for (int e = t; e < M2 * Dd; e += 256) {
            int i = e >> 4, d = e & 15;
            zs[i][d] = g_Zs[p][i][d];
        }
        zn[t] = g_zn[p][t];
        __syncthreads();
        int bl = t & 127, half = t >> 7;
        float xr[Dd];
#pragma unroll
        for (int d = 0; d < Dd; d++) xr[d] = g_Xs[h][b0 + bl][d];
        float xnn = g_xn[h][b0 + bl];
        float sf2 = g_sf2[h];
        for (int ii = 0; ii < 128; ii++) {
            int i = half * 128 + ii;
            float dot = 0.0f;
#pragma unroll
            for (int d = 0; d < Dd; d++) dot += zs[i][d] * xr[d];
            float d2 = fmaxf(zn[i] + xnn - 2.0f * dot, 0.0f);
            g_kx[p][i][b0 + bl] = sf2 * __expf(-0.5f * d2);
        }
    } else {
        // ===== covT1: idx = bid-1024; v = idx&3, p = idx>>2 =====
        float (*Ta)[129] = (float (*)[129])sb;
        float (*Tb)[129] = (float (*)[129])(sb + 2064);
        int idx = bid - 1024;
        int v = idx & 3, p = idx >> 2, o = p % Oo;
        int tx = t & 15, ty = t >> 4;
        float acc[8][8];
#pragma unroll
        for (int m = 0; m < 8; m++)
#pragma unroll
            for (int n = 0; n < 8; n++) acc[m][n] = 0.0f;

        for (int kc = 0; kc < Mm; kc += 16) {
            if (v == 0 || v == 1) {
                for (int e = t; e < 2048; e += 256) {
                    int i = e >> 4, c = e & 15;
                    Ta[c][i] = L_old[(o * Mm + i) * Mm + kc + c];
                }
            } else if (v == 2) {
                for (int e = t; e < 2048; e += 256) {
                    int i = e >> 4, c = e & 15;
                    int k = kc + c;
                    Ta[c][i] = (k <= i) ? u_tril_vec[o * 8256 + (i * (i + 1)) / 2 + k] : 0.0f;
                }
            } else {
                for (int e = t; e < 2048; e += 256) {
                    int kk = e >> 7, q = e & 127;
                    Ta[kk][q] = g_X1[p][kc + kk][q];
                    Tb[kk][q] = g_W11[p][kc + kk][q];
                }
            }
            if (v == 1 || v == 2) {
                for (int e = t; e < 2048; e += 256) {
                    int j = e & 127, kk = e >> 7;
                    Tb[kk][j] = g_AtX[p][kc + kk][j];
                }
            }
            __syncthreads();
            if (v == 0) {
#pragma unroll
                for (int kk = 0; kk < 16; kk++) {
                    float a[8], b[8];
#pragma unroll
                    for (int m = 0; m < 8; m++) a[m] = Ta[kk][ty + 16 * m];
#pragma unroll
                    for (int n = 0; n < 8; n++) b[n] = Ta[kk][tx + 16 * n];
#pragma unroll
                    for (int m = 0; m < 8; m++)
#pragma unroll
                        for (int n = 0; n < 8; n++) acc[m][n] += a[m] * b[n];
                }
            } else if (v == 1) {
#pragma unroll
                for (int kk = 0; kk < 16; kk++) {
                    float a[8], b[8];
#pragma unroll
                    for (int m = 0; m < 8; m++) a[m] = Tb[kk][ty + 16 * m];
#pragma unroll
                    for (int n = 0; n < 8; n++) b[n] = Ta[kk][tx + 16 * n];
#pragma unroll
                    for (int m = 0; m < 8; m++)
#pragma unroll
                        for (int n = 0; n < 8; n++) acc[m][n] += a[m] * b[n];
                }
            } else if (v == 2) {
#pragma unroll
                for (int kk = 0; kk < 16; kk++) {
                    float a[8], b[8], c2[8], d2[8];
#pragma unroll
                    for (int m = 0; m < 8; m++) { a[m] = Ta[kk][ty + 16 * m]; c2[m] = Tb[kk][ty + 16 * m]; }
#pragma unroll
                    for (int n = 0; n < 8; n++) { b[n] = Ta[kk][tx + 16 * n]; d2[n] = Tb[kk][tx + 16 * n]; }
#pragma unroll
                    for (int m = 0; m < 8; m++)
#pragma unroll
                        for (int n = 0; n < 8; n++) acc[m][n] += a[m] * b[n] + c2[m] * d2[n];
                }
            } else {
#pragma unroll
                for (int kk = 0; kk < 16; kk++) {
                    float a[8], b[8];
#pragma unroll
                    for (int m = 0; m < 8; m++) a[m] = Ta[kk][ty + 16 * m];
#pragma unroll
                    for (int n = 0; n < 8; n++) b[n] = Tb[kk][tx + 16 * n];
#pragma unroll
                    for (int m = 0; m < 8; m++)
#pragma unroll
                        for (int n = 0; n < 8; n++) acc[m][n] += a[m] * b[n];
                }
            }
            __syncthreads();
        }

        if (v < 3) {
            int r0 = (v == 0) ? 0 : Mm;
            int c0 = (v == 2) ? Mm : 0;
#pragma unroll
            for (int m = 0; m < 8; m++)
#pragma unroll
                for (int n = 0; n < 8; n++) g_cov[p][r0 + ty + 16 * m][c0 + tx + 16 * n] = acc[m][n];
        } else {
#pragma unroll
            for (int m = 0; m < 8; m++)
#pragma unroll
                for (int n = 0; n < 8; n++) g_T1[p][ty + 16 * m][tx + 16 * n] = acc[m][n];
        }
    }
}

// ---------------- k_BB: fused B1f (blocks 0..127) + B2n' (blocks 128..255) ----------------
__global__ __launch_bounds__(256, 2) void k_BB() {
    extern __shared__ float sm[];
    int t = threadIdx.x;
    int tx = t & 15, ty = t >> 4;

    if (blockIdx.x < HO) {
        float* S    = sm;
        float* stg  = sm + 16512;
        float* dinv = sm + 18560;
        float* mjs  = sm + 18688;
        float* vbuf = sm + 18944;
        int p = blockIdx.x;

        for (int e = t; e < Mm * Mm; e += 256) {
            int i = e >> 7, j = e & 127;
            S[i * LDA + j] = g_schur[p][i][j];
        }
        mjs[t] = g_mj[p][t];
        __syncthreads();
        chol128(S, dinv, t);
        trtri128_blocked(S, dinv, t);

        for (int e = t; e < Mm * Mm; e += 256) {
            int k = e >> 7, i = e & 127;
            g_Wt[p][Mm + k][Mm + i] = S[i * LDA + k];
        }

        float acc[8][8];
#pragma unroll
        for (int m = 0; m < 8; m++)
#pragma unroll
            for (int n = 0; n < 8; n++) acc[m][n] = 0.0f;
        for (int kc = 0; kc < Mm; kc += 16) {
            for (int e = t; e < 2048; e += 256) {
                int kk = e >> 7, q = e & 127;
                stg[kk * 128 + q] = g_T1[p][kc + kk][q];
            }
            __syncthreads();
#pragma unroll
            for (int kk = 0; kk < 16; kk++) {
                float a[8], b[8];
#pragma unroll
                for (int m = 0; m < 8; m++) a[m] = S[(ty + 16 * m) * LDA + kc + kk];
#pragma unroll
                for (int n = 0; n < 8; n++) b[n] = stg[kk * 128 + tx + 16 * n];
#pragma unroll
                for (int m = 0; m < 8; m++)
#pragma unroll
                    for (int n = 0; n < 8; n++) acc[m][n] -= a[m] * b[n];
            }
            __syncthreads();
        }
#pragma unroll
        for (int m = 0; m < 8; m++) {
            float pm = 0.0f;
#pragma unroll
            for (int n = 0; n < 8; n++) {
                int r = ty + 16 * m, j = tx + 16 * n;
                g_Wt[p][j][Mm + r] = acc[m][n];
                pm += acc[m][n] * mjs[j];
            }
            vbuf[(ty + 16 * m) * 16 + tx] = pm;
        }
        __syncthreads();
        if (t < 128) {
            float s = 0.0f;
#pragma unroll
            for (int x2 = 0; x2 < 16; x2++) s += vbuf[t * 16 + x2];
            for (int j = 0; j < Mm; j++) s += S[t * LDA + j] * mjs[Mm + j];
            g_vm[p][Mm + t] = s;
        }
    } else {
        float* C    = sm;
        float (*Ta)[129] = (float (*)[129])(sm + 16512);
        float* dinv = sm + 18576;
        int p = blockIdx.x - HO;

        for (int e = t; e < Mm * Mm; e += 256) {
            int i = e >> 7, j = e & 127;
            float v = g_cov[p][i][j];
            if (i == j) v += JIT;
            C[i * LDA + j] = v;
        }
        __syncthreads();
        chol128(C, dinv, t);
        for (int e = t; e < Mm * Mm; e += 256) {
            int i = e >> 7, k = e & 127;
            g_L11p[p][i][k] = (k <= i) ? C[i * LDA + k] : 0.0f;
        }
        __syncthreads();
        trtri128_blocked(C, dinv, t);

        {
            float acc[8][8];
#pragma unroll
            for (int m = 0; m < 8; m++)
#pragma unroll
                for (int n = 0; n < 8; n++) acc[m][n] = 0.0f;
            for (int kc = 0; kc < Mm; kc += 16) {
                for (int e = t; e < 2048; e += 256) {
                    int r = e >> 4, c = e & 15;
                    Ta[c][r] = g_cov[p][Mm + r][kc + c];
                }
                __syncthreads();
#pragma unroll
                for (int kk = 0; kk < 16; kk++) {
                    float a[8], b[8];
#pragma unroll
                    for (int m = 0; m < 8; m++) a[m] = Ta[kk][ty + 16 * m];
#pragma unroll
                    for (int n = 0; n < 8; n++) b[n] = C[(tx + 16 * n) * LDA + kc + kk];
#pragma unroll
                    for (int m = 0; m < 8; m++)
#pragma unroll
                        for (int n = 0; n < 8; n++) acc[m][n] += a[m] * b[n];
                }
                __syncthreads();
            }
#pragma unroll
            for (int m = 0; m < 8; m++)
#pragma unroll
                for (int n = 0; n < 8; n++) g_L21p[p][ty + 16 * m][tx + 16 * n] = acc[m][n];
        }
        __syncthreads();

        {
            float acc[8][8];
#pragma unroll
            for (int m = 0; m < 8; m++)
#pragma unroll
                for (int n = 0; n < 8; n++) acc[m][n] = 0.0f;
            for (int kc = 0; kc < Mm; kc += 16) {
                for (int e = t; e < 2048; e += 256) {
                    int r = e >> 4, c = e & 15;
                    Ta[c][r] = g_L21p[p][r][kc + c];
                }
                __syncthreads();
#pragma unroll
                for (int kk = 0; kk < 16; kk++) {
                    float a[8], b[8];
#pragma unroll
                    for (int m = 0; m < 8; m++) a[m] = Ta[kk][ty + 16 * m];
#pragma unroll
                    for (int n = 0; n < 8; n++) b[n] = Ta[kk][tx + 16 * n];
#pragma unroll
                    for (int m = 0; m < 8; m++)
#pragma unroll
                        for (int n = 0; n < 8; n++) acc[m][n] += a[m] * b[n];
                }
                __syncthreads();
            }
#pragma unroll
            for (int m = 0; m < 8; m++)
#pragma unroll
                for (int n = 0; n < 8; n++) {
                    int i = ty + 16 * m, j = tx + 16 * n;
                    float v = g_cov[p][Mm + i][Mm + j] - acc[m][n];
                    if (i == j) v += JIT;
                    C[i * LDA + j] = v;
                }
        }
        __syncthreads();
        chol128(C, dinv, t);
        for (int e = t; e < Mm * Mm; e += 256) {
            int i = e >> 7, k = e & 127;
            g_L22p[p][i][k] = (k <= i) ? C[i * LDA + k] : 0.0f;
        }
    }
}

// ---------------- k_RA: gemmA (blocks 0..2047) U k_R (blocks 2048..2431) ----------------
__global__ __launch_bounds__(256) void k_RA() {
    __shared__ __align__(16) float sb[6272];
    int bid = blockIdx.x, t = threadIdx.x;

    if (bid < 2048) {
        float* As = sb;
        float* Bs = sb + 2048;
        float* vs = sb + 4096;
        float* red = sb + 4224;
        int b0 = (bid & 7) * 128, by = (bid >> 3) & 1, p = bid >> 4;
        int i0 = by * 128;
        int tx = t % 16, ty = t / 16;
        if (t < 128) vs[t] = g_vm[p][i0 + t];
        unsigned long long acc[8][4];
#pragma unroll
        for (int m = 0; m < 8; m++)
#pragma unroll
            for (int n = 0; n < 4; n++) acc[m][n] = 0ULL;

        int kmax = i0 + 128;
        for (int kc = 0; kc < kmax; kc += 16) {
#pragma unroll
            for (int e = 0; e < 2; e++) {
                int q = t + e * 256;
                int kk = q >> 5, c4 = q & 31;
                *(float4*)&As[kk * 128 + c4 * 4] = *(const float4*)&g_Wt[p][kc + kk][i0 + c4 * 4];
                *(float4*)&Bs[kk * 128 + c4 * 4] = *(const float4*)&g_kx[p][kc + kk][b0 + c4 * 4];
            }
            __syncthreads();
#pragma unroll
            for (int kk = 0; kk < 16; kk++) {
                float4 a0 = *(const float4*)&As[kk * 128 + ty * 8];
                float4 a1 = *(const float4*)&As[kk * 128 + ty * 8 + 4];
                float4 q0 = *(const float4*)&Bs[kk * 128 + tx * 8];
                float4 q1 = *(const float4*)&Bs[kk * 128 + tx * 8 + 4];
                unsigned long long bp[4] = { pk2(q0.x, q0.y), pk2(q0.z, q0.w), pk2(q1.x, q1.y), pk2(q1.z, q1.w) };
                float am[8] = { a0.x, a0.y, a0.z, a0.w, a1.x, a1.y, a1.z, a1.w };
#pragma unroll
                for (int m = 0; m < 8; m++) {
                    unsigned long long ad = pk2(am[m], am[m]);
#pragma unroll
                    for (int n = 0; n < 4; n++) acc[m][n] = ffma2(ad, bp[n], acc[m][n]);
                }
            }
            __syncthreads();
        }
        float av[8][8];
#pragma unroll
        for (int m = 0; m < 8; m++) {
#pragma unroll
            for (int n = 0; n < 4; n++) {
                float2 v = upk2(acc[m][n]);
                av[m][n * 2] = v.x; av[m][n * 2 + 1] = v.y;
            }
            *(float4*)&g_a[p][i0 + ty * 8 + m][b0 + tx * 8]     = make_float4(av[m][0], av[m][1], av[m][2], av[m][3]);
            *(float4*)&g_a[p][i0 + ty * 8 + m][b0 + tx * 8 + 4] = make_float4(av[m][4], av[m][5], av[m][6], av[m][7]);
        }
#pragma unroll
        for (int n = 0; n < 8; n++) {
            float s = 0.0f;
#pragma unroll
            for (int m = 0; m < 8; m++) s += av[m][n] * av[m][n];
            red[ty * 128 + tx * 8 + n] = s;
        }
        __syncthreads();
        if (t < 128) {
            float s = 0.0f;
#pragma unroll
            for (int y = 0; y < 16; y++) s += red[y * 128 + t];
            g_d1p[by][p][b0 + t] = s;
        }
        __syncthreads();
#pragma unroll
        for (int n = 0; n < 8; n++) {
            float s = 0.0f;
#pragma unroll
            for (int m = 0; m < 8; m++) s += vs[ty * 8 + m] * av[m][n];
            red[ty * 128 + tx * 8 + n] = s;
        }
        __syncthreads();
        if (t < 128) {
            float s = 0.0f;
#pragma unroll
            for (int y = 0; y < 16; y++) s += red[y * 128 + t];
            g_mup[by][p][b0 + t] = s;
        }
    } else {
        float* As = sb;
        float* Bs = sb + 2048;
        int r = bid - 2048;
        int v = r / HO, p = r % HO;
        int tx = t & 15, ty = t >> 4;
        float acc[8][8];
#pragma unroll
        for (int m = 0; m < 8; m++)
#pragma unroll
            for (int n = 0; n < 8; n++) acc[m][n] = 0.0f;

        int kTot = (v == 1) ? M2 : Mm;
        for (int kc = 0; kc < kTot; kc += 16) {
            for (int e = t; e < 2048; e += 256) {
                int kk = e >> 7, q = e & 127;
                int kg = kc + kk;
                float av, bv;
                if (v == 0) { av = g_Wt[p][kg][q];            bv = g_L11p[p][kg][q]; }
                else if (v == 1) {
                    av = g_Wt[p][kg][Mm + q];
                    bv = (kg < Mm) ? g_L11p[p][kg][q] : g_L21p[p][kg - Mm][q];
                }
                else { av = g_Wt[p][Mm + kg][Mm + q];         bv = g_L22p[p][kg][q]; }
                As[kk * 128 + q] = av;
                Bs[kk * 128 + q] = bv;
            }
            __syncthreads();
#pragma unroll
            for (int kk = 0; kk < 16; kk++) {
                float4 a0 = *(const float4*)&As[kk * 128 + ty * 8];
                float4 a1 = *(const float4*)&As[kk * 128 + ty * 8 + 4];
                float4 b0 = *(const float4*)&Bs[kk * 128 + tx * 8];
                float4 b1 = *(const float4*)&Bs[kk * 128 + tx * 8 + 4];
                float am[8] = { a0.x, a0.y, a0.z, a0.w, a1.x, a1.y, a1.z, a1.w };
                float bn[8] = { b0.x, b0.y, b0.z, b0.w, b1.x, b1.y, b1.z, b1.w };
#pragma unroll
                for (int m = 0; m < 8; m++)
#pragma unroll
                    for (int n = 0; n < 8; n++) acc[m][n] += am[m] * bn[n];
            }
            __syncthreads();
        }
        int r0 = (v == 0) ? 0 : Mm;
        int c0 = (v == 2) ? Mm : 0;
#pragma unroll
        for (int m = 0; m < 8; m++) {
            *(float4*)&g_R[p][r0 + ty * 8 + m][c0 + tx * 8]     = make_float4(acc[m][0], acc[m][1], acc[m][2], acc[m][3]);
            *(float4*)&g_R[p][r0 + ty * 8 + m][c0 + tx * 8 + 4] = make_float4(acc[m][4], acc[m][5], acc[m][6], acc[m][7]);
        }
    }
}

// ---------------- gemmH: h = R^T @ a, d2 partials (FFMA2) ----------------
__global__ __launch_bounds__(256) void k_gemmH() {
    __shared__ float As[16][128];
    __shared__ float Bs[16][128];
    __shared__ float red[16][128];
    int p = blockIdx.z;
    int j0 = blockIdx.y * 128, b0 = blockIdx.x * 128;
    int t = threadIdx.x, tx = t % 16, ty = t / 16;
    unsigned long long acc[8][4];
#pragma unroll
    for (int m = 0; m < 8; m++)
#pragma unroll
        for (int n = 0; n < 4; n++) acc[m][n] = 0ULL;

    for (int kc = j0; kc < M2; kc += 16) {
#pragma unroll
        for (int e = 0; e < 2; e++) {
            int q = t + e * 256;
            int kk = q >> 5, c4 = q & 31;
            *(float4*)&As[kk][c4 * 4] = *(const float4*)&g_R[p][kc + kk][j0 + c4 * 4];
            *(float4*)&Bs[kk][c4 * 4] = *(const float4*)&g_a[p][kc + kk][b0 + c4 * 4];
        }
        __syncthreads();
#pragma unroll
        for (int kk = 0; kk < 16; kk++) {
            float4 a0 = *(const float4*)&As[kk][ty * 8];
            float4 a1 = *(const float4*)&As[kk][ty * 8 + 4];
            float4 q0 = *(const float4*)&Bs[kk][tx * 8];
            float4 q1 = *(const float4*)&Bs[kk][tx * 8 + 4];
            unsigned long long bp[4] = { pk2(q0.x, q0.y), pk2(q0.z, q0.w), pk2(q1.x, q1.y), pk2(q1.z, q1.w) };
            float am[8] = { a0.x, a0.y, a0.z, a0.w, a1.x, a1.y, a1.z, a1.w };
#pragma unroll
            for (int m = 0; m < 8; m++) {
                unsigned long long ad = pk2(am[m], am[m]);
#pragma unroll
                for (int n = 0; n < 4; n++) acc[m][n] = ffma2(ad, bp[n], acc[m][n]);
            }
        }
        __syncthreads();
    }
#pragma unroll
    for (int n = 0; n < 8; n++) {
        float s = 0.0f;
#pragma unroll
        for (int m = 0; m < 8; m++) {
            float2 v = upk2(acc[m][n / 2]);
            float h = (n & 1) ? v.y : v.x;
            s += h * h;
        }
        red[ty][tx * 8 + n] = s;
    }
    __syncthreads();
    if (t < 128) {
        float s = 0.0f;
#pragma unroll
        for (int y = 0; y < 16; y++) s += red[y][t];
        g_d2p[blockIdx.y][p][b0 + t] = s;
    }
}

// ---------------- final ----------------
__global__ void k_final(float* __restrict__ out) {
    int idx = blockIdx.x * 256 + threadIdx.x;
    if (idx >= HOB) return;
    int p = idx / Bb, b = idx % Bb;
    out[idx] = g_mup[0][p][b] + g_mup[1][p][b];
    out[HOB + idx] = g_sf2[p / Oo] - (g_d1p[0][p][b] + g_d1p[1][p][b]) + (g_d2p[0][p][b] + g_d2p[1][p][b]);
}

extern "C" void kernel_launch(void* const* d_in, const int* in_sizes, int n_in,
                              void* d_out, int out_size) {
    const float* x          = (const float*)d_in[0];
    const float* z          = (const float*)d_in[1];
    const float* u_mean     = (const float*)d_in[2];
    const float* u_tril_vec = (const float*)d_in[3];
    const float* m_old      = (const float*)d_in[4];
    const float* L_old      = (const float*)d_in[5];
    const float* z_old      = (const float*)d_in[6];
    const float* theta      = (const float*)d_in[7];
    float* out = (float*)d_out;

    static bool init_done = false;
    if (!init_done) {
        cudaFuncSetAttribute(k_stageA, cudaFuncAttributeMaxDynamicSharedMemorySize, 207872);
        cudaFuncSetAttribute(k_BB,     cudaFuncAttributeMaxDynamicSharedMemorySize, 83968);
        init_done = true;
    }

    // single stream; stageA stays at host-launch slot 3 for the profiler
    k_prep_theta<<<1, 128>>>(theta);
    k_prep_z<<<HO, 256>>>(z, z_old);
    k_kuu2<<<dim3(16, HO), 256>>>();
    k_stageA<<<HO, 512, 207872>>>(m_old, L_old, u_mean, u_tril_vec);
    k_prep_x<<<16, 256>>>(x);
    k_mid<<<1536, 256>>>(L_old, u_tril_vec);
    k_BB<<<2 * HO, 256, 83968>>>();
    k_RA<<<2432, 256>>>();
    k_gemmH<<<dim3(8, 2, HO), 256>>>();
    k_final<<<512, 256>>>(out);
}